// round 12
// baseline (speedup 1.0000x reference)
#include <cuda_runtime.h>
#include <cuda_fp16.h>
#include <math.h>
#include <stdint.h>

// Problem constants
#define BATCH 8192
#define SDIM  70
#define NS    64
#define HID   1024
#define NACT  4096
#define K1PAD 128                        // K=70 zero-padded for HMMA layer 1
#define LOG_EPS (-20.723265836946407f)   // logf(1e-9f)

// ---------------------------------------------------------------------------
// Scratch (allocation-free __device__ globals)
// ---------------------------------------------------------------------------
__device__ __align__(16) __half g_sp[BATCH * K1PAD];    // states fp16, K-padded
__device__ __align__(16) __half g_W1T[HID * K1PAD];     // W1^T fp16, K-padded
__device__ __align__(16) __half g_h1[BATCH * HID];
__device__ __align__(16) __half g_h2[BATCH * HID];
__device__ __align__(16) __half g_W2T[HID * HID];
__device__ __align__(16) __half g_WhT[NACT * HID];
__device__ __align__(16) __half g_lg[BATCH * NACT];     // fp16 logits (unmasked)

// ---------------------------------------------------------------------------
// Helpers (plain sm_80+ PTX only — nothing sm_103a-conditional)
// ---------------------------------------------------------------------------
__device__ __forceinline__ uint32_t smem_u32(const void* p) {
    uint32_t a;
    asm("{ .reg .u64 t; cvta.to.shared.u64 t, %1; cvt.u32.u64 %0, t; }" : "=r"(a) : "l"(p));
    return a;
}

__device__ __forceinline__ void cp_async16(uint32_t saddr, const void* gaddr) {
    asm volatile("cp.async.cg.shared.global [%0], [%1], 16;" :: "r"(saddr), "l"(gaddr));
}
#define CP_COMMIT()  asm volatile("cp.async.commit_group;" ::: "memory")
#define CP_WAIT(n)   asm volatile("cp.async.wait_group %0;" :: "n"(n) : "memory")

__device__ __forceinline__ void ldsm_x4(uint32_t* r, uint32_t addr) {
    asm volatile("ldmatrix.sync.aligned.m8n8.x4.shared.b16 {%0,%1,%2,%3}, [%4];"
        : "=r"(r[0]), "=r"(r[1]), "=r"(r[2]), "=r"(r[3]) : "r"(addr));
}

__device__ __forceinline__ void mma16816(float* d, const uint32_t* a, const uint32_t* b) {
    asm volatile("mma.sync.aligned.m16n8k16.row.col.f32.f16.f16.f32 "
        "{%0,%1,%2,%3}, {%4,%5,%6,%7}, {%8,%9}, {%0,%1,%2,%3};"
        : "+f"(d[0]), "+f"(d[1]), "+f"(d[2]), "+f"(d[3])
        : "r"(a[0]), "r"(a[1]), "r"(a[2]), "r"(a[3]), "r"(b[0]), "r"(b[1]));
}

// ---------------------------------------------------------------------------
// HMMA GEMM (single fp16), NST = K/64 as a template parameter:
//   OUT==0: Ch = (A @ B^T + bias) as fp16  (plain logits)
//   OUT==1: Ch = tanh(A @ B^T + bias) as fp16
// CTA tile 128x128, 128 threads: 4 warps in 2(m) x 2(n), warp tile 64 x 64.
// Smem reads per K-tile: A x2 + B x2 (vs x2/x4 before) -> smem decongested.
// 3-stage cp.async ring, ONE __syncthreads per K-tile, fully unrolled,
// double-buffered fragments across k16 sub-steps. 2 CTAs/SM.
// XOR-8 swizzled 128B smem rows.
// ---------------------------------------------------------------------------
#define KT 64
#define A_BYTES  16384                 // 128 rows x 128 B
#define STAGE_BYTES (2 * A_BYTES)      // A + B = 32768
#define NSTAGE 3
#define HMMA_SMEM (NSTAGE * STAGE_BYTES)   // 98304

template <int OUT, int NST>
__global__ __launch_bounds__(128, 2)
void hmma_gemm(const __half* __restrict__ A, const __half* __restrict__ B,
               const float* __restrict__ bias,
               __half* __restrict__ Ch, int Ntot)
{
    constexpr int K = NST * KT;
    extern __shared__ char smem_raw[];
    const uint32_t sbase = smem_u32(smem_raw);

    const int tid  = threadIdx.x;
    const int lane = tid & 31;
    const int wid  = tid >> 5;
    const int wm   = wid & 1;          // 2 warps along M (64 rows each)
    const int wn   = wid >> 1;         // 2 warps along N (64 cols each)
    const int bm   = blockIdx.y * 128;
    const int bn   = blockIdx.x * 128;

    float acc[4][8][4];
#pragma unroll
    for (int i = 0; i < 4; i++)
#pragma unroll
        for (int j = 0; j < 8; j++)
#pragma unroll
            for (int q = 0; q < 4; q++) acc[i][j][q] = 0.0f;

    // ---- stage loader: 2 x 1024 16B chunks (A, B), 16 per thread ------------
    auto load_stage = [&](int i, int s) {
        const int kl = i * KT;
        const uint32_t sA = sbase + s * STAGE_BYTES;
        const uint32_t sB = sA + A_BYTES;
#pragma unroll
        for (int p = 0; p < 8; p++) {
            const int idx = p * 128 + tid;
            const int r = idx >> 3, c = idx & 7;
            const uint32_t so = r * 128 + ((c ^ (r & 7)) << 4);
            cp_async16(sA + so, A + (size_t)(bm + r) * K + kl + c * 8);
            cp_async16(sB + so, B + (size_t)(bn + r) * K + kl + c * 8);
        }
        CP_COMMIT();
    };

    // fragment loader (4 A m16 tiles + 4 B n16 groups per k16 step)
    auto ld_frags = [&](uint32_t sA, uint32_t sB, int ks,
                        uint32_t a[4][4], uint32_t b[4][4]) {
#pragma unroll
        for (int mt = 0; mt < 4; mt++) {
            const int row = wm * 64 + mt * 16 + (lane & 15);
            const int ch  = ks * 2 + (lane >> 4);
            ldsm_x4(a[mt], sA + row * 128 + ((ch ^ (row & 7)) << 4));
        }
#pragma unroll
        for (int np = 0; np < 4; np++) {
            const int nrow = wn * 64 + np * 16 + ((lane >> 4) << 3) + (lane & 7);
            const int ch   = ks * 2 + ((lane >> 3) & 1);
            ldsm_x4(b[np], sB + nrow * 128 + ((ch ^ (nrow & 7)) << 4));
        }
    };

    load_stage(0, 0);
    if (NST > 1) load_stage(1, 1);

#pragma unroll
    for (int i = 0; i < NST; i++) {
        const int s = i % NSTAGE;
        if (i + 1 < NST) { CP_WAIT(1); } else { CP_WAIT(0); }
        __syncthreads();

        // refill the slot drained at iter i-1 (stage i+2 -> slot (i+2)%3)
        if (i + 2 < NST) load_stage(i + 2, (i + 2) % NSTAGE);

        const uint32_t sA = sbase + s * STAGE_BYTES;
        const uint32_t sB = sA + A_BYTES;

        uint32_t af[2][4][4], bf[2][4][4];
        ld_frags(sA, sB, 0, af[0], bf[0]);
#pragma unroll
        for (int ks = 0; ks < KT / 16; ks++) {
            const int cur = ks & 1;
            if (ks + 1 < KT / 16) ld_frags(sA, sB, ks + 1, af[cur ^ 1], bf[cur ^ 1]);
#pragma unroll
            for (int mt = 0; mt < 4; mt++)
#pragma unroll
                for (int np = 0; np < 4; np++) {
                    mma16816(acc[mt][np * 2 + 0], af[cur][mt], &bf[cur][np][0]);
                    mma16816(acc[mt][np * 2 + 1], af[cur][mt], &bf[cur][np][2]);
                }
        }
    }

    // ---- epilogue ----
    const int q  = lane & 3;
    const int r4 = lane >> 2;
#pragma unroll
    for (int mt = 0; mt < 4; mt++) {
#pragma unroll
        for (int nt = 0; nt < 8; nt++) {
            const int row0 = bm + wm * 64 + mt * 16 + r4;
            const int col  = bn + wn * 64 + nt * 8 + q * 2;
            const float b0 = bias[col], b1 = bias[col + 1];
            float d0 = acc[mt][nt][0] + b0;
            float d1 = acc[mt][nt][1] + b1;
            float d2 = acc[mt][nt][2] + b0;
            float d3 = acc[mt][nt][3] + b1;
            if (OUT == 1) {
                d0 = tanhf(d0); d1 = tanhf(d1); d2 = tanhf(d2); d3 = tanhf(d3);
            }
            *reinterpret_cast<__half2*>(Ch + (size_t)row0 * Ntot + col) =
                __halves2half2(__float2half_rn(d0), __float2half_rn(d1));
            *reinterpret_cast<__half2*>(Ch + (size_t)(row0 + 8) * Ntot + col) =
                __halves2half2(__float2half_rn(d2), __float2half_rn(d3));
        }
    }
}

// ---------------------------------------------------------------------------
// Prep kernels
// ---------------------------------------------------------------------------
__global__ __launch_bounds__(256)
void pad_states(const float* __restrict__ S, __half* __restrict__ P)
{
    const int idx = blockIdx.x * 256 + threadIdx.x;
    const int m = idx >> 7, k = idx & 127;
    if (m < BATCH)
        P[idx] = (k < SDIM) ? __float2half_rn(S[(size_t)m * SDIM + k]) : __half(0.0f);
}

__global__ __launch_bounds__(256)
void pad_w1t(const float* __restrict__ W, __half* __restrict__ T)
{
    const int idx = blockIdx.x * 256 + threadIdx.x;
    const int n = idx >> 7, k = idx & 127;
    if (n < HID)
        T[idx] = (k < SDIM) ? __float2half_rn(W[(size_t)k * HID + n]) : __half(0.0f);
}

// W[K,N] fp32 -> Wt [N,K] fp16; 64(k) x 32(n) tiles, half2 stores.
__global__ __launch_bounds__(256)
void transpose_half(const float* __restrict__ W,
                    __half* __restrict__ T, int K, int N)
{
    __shared__ float t[64][33];
    const int k0 = blockIdx.x * 64, n0 = blockIdx.y * 32;
    const int tx = threadIdx.x, ty = threadIdx.y;   // 32 x 8
#pragma unroll
    for (int j = 0; j < 8; j++)
        t[ty * 8 + j][tx] = W[(size_t)(k0 + ty * 8 + j) * N + n0 + tx];
    __syncthreads();
#pragma unroll
    for (int j = 0; j < 4; j++) {
        const int n = ty + j * 8;
        __half2 v = __halves2half2(__float2half_rn(t[tx * 2][n]),
                                   __float2half_rn(t[tx * 2 + 1][n]));
        *reinterpret_cast<__half2*>(&T[(size_t)(n0 + n) * K + k0 + tx * 2]) = v;
    }
}

// ---------------------------------------------------------------------------
// Masked softmax: fp16 logits -> fp32 probabilities (mask via base-4 digits)
// ---------------------------------------------------------------------------
__global__ __launch_bounds__(256)
void masked_softmax_h(const __half* __restrict__ lg, float* __restrict__ out,
                      const float* __restrict__ states)
{
    const int row = blockIdx.x;
    const int tid = threadIdx.x;

    __shared__ float sred[32];
    __shared__ int scap[6];

    if (tid < 6) scap[tid] = (int)floorf(states[(size_t)row * SDIM + NS + tid]);
    __syncthreads();

    const int c0 = scap[0], c1 = scap[1], c2 = scap[2];
    const int c3 = scap[3], c4 = scap[4], c5 = scap[5];

    const __half* rowp = lg + (size_t)row * NACT;
    float* outp = out + (size_t)row * NACT;
    const int base = tid * 16;

    float vals[16];
    float mx = -INFINITY;

#pragma unroll
    for (int h = 0; h < 8; h++) {
        float2 f = __half22float2(reinterpret_cast<const __half2*>(rowp + base)[h]);
        vals[2 * h]     = f.x;
        vals[2 * h + 1] = f.y;
    }
#pragma unroll
    for (int c = 0; c < 16; c++) {
        const int a = base + c;
        bool feas = (((a >> 10) & 3) <= c0) && (((a >> 8) & 3) <= c1) &&
                    (((a >> 6)  & 3) <= c2) && (((a >> 4) & 3) <= c3) &&
                    (((a >> 2)  & 3) <= c4) && (((a)      & 3) <= c5);
        if (!feas) vals[c] += LOG_EPS;
        mx = fmaxf(mx, vals[c]);
    }

#pragma unroll
    for (int o = 16; o > 0; o >>= 1) mx = fmaxf(mx, __shfl_xor_sync(0xffffffffu, mx, o));
    if ((tid & 31) == 0) sred[tid >> 5] = mx;
    __syncthreads();
    if (tid < 32) {
        float m = (tid < 8) ? sred[tid] : -INFINITY;
#pragma unroll
        for (int o = 4; o > 0; o >>= 1) m = fmaxf(m, __shfl_xor_sync(0xffffffffu, m, o));
        if (tid == 0) sred[0] = m;
    }
    __syncthreads();
    mx = sred[0];
    __syncthreads();

    float sum = 0.0f;
#pragma unroll
    for (int i = 0; i < 16; i++) { vals[i] = expf(vals[i] - mx); sum += vals[i]; }

#pragma unroll
    for (int o = 16; o > 0; o >>= 1) sum += __shfl_xor_sync(0xffffffffu, sum, o);
    if ((tid & 31) == 0) sred[tid >> 5] = sum;
    __syncthreads();
    if (tid < 32) {
        float s = (tid < 8) ? sred[tid] : 0.0f;
#pragma unroll
        for (int o = 4; o > 0; o >>= 1) s += __shfl_xor_sync(0xffffffffu, s, o);
        if (tid == 0) sred[0] = s;
    }
    __syncthreads();
    const float inv = 1.0f / sred[0];

#pragma unroll
    for (int v4i = 0; v4i < 4; v4i++) {
        float4 o4;
        o4.x = vals[v4i * 4 + 0] * inv;
        o4.y = vals[v4i * 4 + 1] * inv;
        o4.z = vals[v4i * 4 + 2] * inv;
        o4.w = vals[v4i * 4 + 3] * inv;
        *reinterpret_cast<float4*>(outp + base + v4i * 4) = o4;
    }
}

// ---------------------------------------------------------------------------
extern "C" void kernel_launch(void* const* d_in, const int* in_sizes, int n_in,
                              void* d_out, int out_size)
{
    const float* states = (const float*)d_in[0];
    const float* W1     = (const float*)d_in[1];
    const float* b1     = (const float*)d_in[2];
    const float* W2     = (const float*)d_in[3];
    const float* b2     = (const float*)d_in[4];
    const float* Wh     = (const float*)d_in[5];
    const float* bh     = (const float*)d_in[6];
    float* out = (float*)d_out;

    __half *sp, *W1T, *h1, *h2, *W2T, *WhT, *lg;
    cudaGetSymbolAddress((void**)&sp,  g_sp);
    cudaGetSymbolAddress((void**)&W1T, g_W1T);
    cudaGetSymbolAddress((void**)&h1,  g_h1);
    cudaGetSymbolAddress((void**)&h2,  g_h2);
    cudaGetSymbolAddress((void**)&W2T, g_W2T);
    cudaGetSymbolAddress((void**)&WhT, g_WhT);
    cudaGetSymbolAddress((void**)&lg,  g_lg);

    cudaFuncSetAttribute((const void*)hmma_gemm<1, 2>,
                         cudaFuncAttributeMaxDynamicSharedMemorySize, HMMA_SMEM);
    cudaFuncSetAttribute((const void*)hmma_gemm<1, 16>,
                         cudaFuncAttributeMaxDynamicSharedMemorySize, HMMA_SMEM);
    cudaFuncSetAttribute((const void*)hmma_gemm<0, 16>,
                         cudaFuncAttributeMaxDynamicSharedMemorySize, HMMA_SMEM);

    // prep: pad states + W1^T, transpose W2/Wh to fp16 K-major
    pad_states<<<(BATCH * K1PAD) / 256, 256>>>(states, sp);
    pad_w1t<<<(HID * K1PAD) / 256, 256>>>(W1, W1T);
    transpose_half<<<dim3(HID / 64, HID / 32), dim3(32, 8)>>>(W2, W2T, HID, HID);
    transpose_half<<<dim3(HID / 64, NACT / 32), dim3(32, 8)>>>(Wh, WhT, HID, NACT);

    // layer 1 (HMMA, K=128 padded) -> h1 fp16
    hmma_gemm<1, 2><<<dim3(HID / 128, BATCH / 128), 128, HMMA_SMEM>>>(
        sp, W1T, b1, h1, HID);
    // layer 2 (HMMA) -> h2 fp16
    hmma_gemm<1, 16><<<dim3(HID / 128, BATCH / 128), 128, HMMA_SMEM>>>(
        h1, W2T, b2, h2, HID);
    // head (HMMA) -> plain fp16 logits
    hmma_gemm<0, 16><<<dim3(NACT / 128, BATCH / 128), 128, HMMA_SMEM>>>(
        h2, WhT, bh, lg, NACT);
    // masked softmax: fp16 logits + states -> fp32 probabilities
    masked_softmax_h<<<BATCH, 256>>>(lg, out, states);
}

// round 13
// speedup vs baseline: 1.0431x; 1.0431x over previous
#include <cuda_runtime.h>
#include <cuda_fp16.h>
#include <math.h>
#include <stdint.h>

// Problem constants
#define BATCH 8192
#define SDIM  70
#define NS    64
#define HID   1024
#define NACT  4096
#define K1PAD 128                        // K=70 zero-padded for HMMA layer 1
#define LOG_EPS (-20.723265836946407f)   // logf(1e-9f)

// ---------------------------------------------------------------------------
// Scratch (allocation-free __device__ globals)
// ---------------------------------------------------------------------------
__device__ __align__(16) __half g_sp[BATCH * K1PAD];    // states fp16, K-padded
__device__ __align__(16) __half g_W1T[HID * K1PAD];     // W1^T fp16, K-padded
__device__ __align__(16) __half g_h1[BATCH * HID];
__device__ __align__(16) __half g_h2[BATCH * HID];
__device__ __align__(16) __half g_W2T[HID * HID];
__device__ __align__(16) __half g_WhT[NACT * HID];
__device__ __align__(16) __half g_lg[BATCH * NACT];     // fp16 logits (unmasked)

// ---------------------------------------------------------------------------
// Helpers (plain sm_80+ PTX only — nothing sm_103a-conditional)
// ---------------------------------------------------------------------------
__device__ __forceinline__ uint32_t smem_u32(const void* p) {
    uint32_t a;
    asm("{ .reg .u64 t; cvta.to.shared.u64 t, %1; cvt.u32.u64 %0, t; }" : "=r"(a) : "l"(p));
    return a;
}

__device__ __forceinline__ void cp_async16(uint32_t saddr, const void* gaddr) {
    asm volatile("cp.async.cg.shared.global [%0], [%1], 16;" :: "r"(saddr), "l"(gaddr));
}
#define CP_COMMIT()  asm volatile("cp.async.commit_group;" ::: "memory")
#define CP_WAIT(n)   asm volatile("cp.async.wait_group %0;" :: "n"(n) : "memory")

__device__ __forceinline__ void ldsm_x4(uint32_t* r, uint32_t addr) {
    asm volatile("ldmatrix.sync.aligned.m8n8.x4.shared.b16 {%0,%1,%2,%3}, [%4];"
        : "=r"(r[0]), "=r"(r[1]), "=r"(r[2]), "=r"(r[3]) : "r"(addr));
}

__device__ __forceinline__ void mma16816(float* d, const uint32_t* a, const uint32_t* b) {
    asm volatile("mma.sync.aligned.m16n8k16.row.col.f32.f16.f16.f32 "
        "{%0,%1,%2,%3}, {%4,%5,%6,%7}, {%8,%9}, {%0,%1,%2,%3};"
        : "+f"(d[0]), "+f"(d[1]), "+f"(d[2]), "+f"(d[3])
        : "r"(a[0]), "r"(a[1]), "r"(a[2]), "r"(a[3]), "r"(b[0]), "r"(b[1]));
}

// ---------------------------------------------------------------------------
// HMMA GEMM (single fp16) — R11-proven configuration, locked:
//   OUT==0: Ch = (A @ B^T + bias) as fp16  (plain logits)
//   OUT==1: Ch = tanh(A @ B^T + bias) as fp16
// CTA tile 128x128, 256 threads, 8 warps in 4(m) x 2(n); warp tile 32 x 64.
// 3-stage cp.async ring, ONE __syncthreads per K-tile, fully unrolled.
// XOR-8 swizzled 128B smem rows. 2 CTAs/SM.
// ---------------------------------------------------------------------------
#define KT 64
#define A_BYTES  16384                 // 128 rows x 128 B
#define STAGE_BYTES (2 * A_BYTES)      // A + B = 32768
#define NSTAGE 3
#define HMMA_SMEM (NSTAGE * STAGE_BYTES)   // 98304

template <int OUT, int NST>
__global__ __launch_bounds__(256, 2)
void hmma_gemm(const __half* __restrict__ A, const __half* __restrict__ B,
               const float* __restrict__ bias,
               __half* __restrict__ Ch, int Ntot)
{
    constexpr int K = NST * KT;
    extern __shared__ char smem_raw[];
    const uint32_t sbase = smem_u32(smem_raw);

    const int tid  = threadIdx.x;
    const int lane = tid & 31;
    const int wid  = tid >> 5;
    const int wm   = wid & 3;          // 4 warps along M (32 rows each)
    const int wn   = wid >> 2;         // 2 warps along N (64 cols each)
    const int bm   = blockIdx.y * 128;
    const int bn   = blockIdx.x * 128;

    float acc[2][8][4];
#pragma unroll
    for (int i = 0; i < 2; i++)
#pragma unroll
        for (int j = 0; j < 8; j++)
#pragma unroll
            for (int q = 0; q < 4; q++) acc[i][j][q] = 0.0f;

    // ---- stage loader: 2 x 1024 16B chunks (A, B), 8 per thread -------------
    auto load_stage = [&](int i, int s) {
        const int kl = i * KT;
        const uint32_t sA = sbase + s * STAGE_BYTES;
        const uint32_t sB = sA + A_BYTES;
#pragma unroll
        for (int p = 0; p < 4; p++) {
            const int idx = p * 256 + tid;
            const int r = idx >> 3, c = idx & 7;
            const uint32_t so = r * 128 + ((c ^ (r & 7)) << 4);
            cp_async16(sA + so, A + (size_t)(bm + r) * K + kl + c * 8);
            cp_async16(sB + so, B + (size_t)(bn + r) * K + kl + c * 8);
        }
        CP_COMMIT();
    };

    load_stage(0, 0);
    if (NST > 1) load_stage(1, 1);

#pragma unroll
    for (int i = 0; i < NST; i++) {
        const int s = i % NSTAGE;
        if (i + 1 < NST) { CP_WAIT(1); } else { CP_WAIT(0); }
        __syncthreads();

        // refill the slot drained at iter i-1 (stage i+2 -> slot (i+2)%3)
        if (i + 2 < NST) load_stage(i + 2, (i + 2) % NSTAGE);

        const uint32_t sA = sbase + s * STAGE_BYTES;
        const uint32_t sB = sA + A_BYTES;

#pragma unroll
        for (int ks = 0; ks < KT / 16; ks++) {
            // A fragments: 2 m16 tiles
            uint32_t a[2][4];
#pragma unroll
            for (int mt = 0; mt < 2; mt++) {
                const int row = wm * 32 + mt * 16 + (lane & 15);
                const int ch  = ks * 2 + (lane >> 4);
                ldsm_x4(a[mt], sA + row * 128 + ((ch ^ (row & 7)) << 4));
            }
            // B fragments: 4 x ldmatrix.x4
            uint32_t b[4][4];
#pragma unroll
            for (int np = 0; np < 4; np++) {
                const int nrow = wn * 64 + np * 16 + ((lane >> 4) << 3) + (lane & 7);
                const int ch   = ks * 2 + ((lane >> 3) & 1);
                ldsm_x4(b[np], sB + nrow * 128 + ((ch ^ (nrow & 7)) << 4));
            }
#pragma unroll
            for (int mt = 0; mt < 2; mt++)
#pragma unroll
                for (int np = 0; np < 4; np++) {
                    mma16816(acc[mt][np * 2 + 0], a[mt], &b[np][0]);
                    mma16816(acc[mt][np * 2 + 1], a[mt], &b[np][2]);
                }
        }
    }

    // ---- epilogue ----
    const int q  = lane & 3;
    const int r4 = lane >> 2;
#pragma unroll
    for (int mt = 0; mt < 2; mt++) {
#pragma unroll
        for (int nt = 0; nt < 8; nt++) {
            const int row0 = bm + wm * 32 + mt * 16 + r4;
            const int col  = bn + wn * 64 + nt * 8 + q * 2;
            const float b0 = bias[col], b1 = bias[col + 1];
            float d0 = acc[mt][nt][0] + b0;
            float d1 = acc[mt][nt][1] + b1;
            float d2 = acc[mt][nt][2] + b0;
            float d3 = acc[mt][nt][3] + b1;
            if (OUT == 1) {
                d0 = tanhf(d0); d1 = tanhf(d1); d2 = tanhf(d2); d3 = tanhf(d3);
            }
            *reinterpret_cast<__half2*>(Ch + (size_t)row0 * Ntot + col) =
                __halves2half2(__float2half_rn(d0), __float2half_rn(d1));
            *reinterpret_cast<__half2*>(Ch + (size_t)(row0 + 8) * Ntot + col) =
                __halves2half2(__float2half_rn(d2), __float2half_rn(d3));
        }
    }
}

// ---------------------------------------------------------------------------
// Fused prep: one grid, block-range dispatch.
//   [0, 4096)        pad states -> g_sp
//   [4096, 4608)     pad W1^T   -> g_W1T
//   [4608, 5120)     transpose W2 (16 k-tiles x 32 n-tiles)
//   [5120, 7168)     transpose Wh (16 k-tiles x 128 n-tiles)
// ---------------------------------------------------------------------------
#define PREP_BLOCKS 7168

__global__ __launch_bounds__(256)
void prep_all(const float* __restrict__ S,  const float* __restrict__ W1,
              const float* __restrict__ W2, const float* __restrict__ Wh,
              __half* __restrict__ sp, __half* __restrict__ W1T,
              __half* __restrict__ W2T, __half* __restrict__ WhT)
{
    __shared__ float t[64][33];
    const int blk = blockIdx.x;
    const int tid = threadIdx.x;

    if (blk < 4096) {
        // pad states
        const int idx = blk * 256 + tid;
        const int m = idx >> 7, k = idx & 127;
        sp[idx] = (k < SDIM) ? __float2half_rn(S[(size_t)m * SDIM + k]) : __half(0.0f);
    } else if (blk < 4608) {
        // pad W1^T
        const int idx = (blk - 4096) * 256 + tid;
        const int n = idx >> 7, k = idx & 127;
        W1T[idx] = (k < SDIM) ? __float2half_rn(W1[(size_t)k * HID + n]) : __half(0.0f);
    } else {
        // transpose: W[K=1024, N] -> T[N, 1024]; 64(k) x 32(n) tiles
        const float* W; __half* T; int N, tile;
        if (blk < 5120) { W = W2; T = W2T; N = HID;  tile = blk - 4608; }
        else            { W = Wh; T = WhT; N = NACT; tile = blk - 5120; }
        const int k0 = (tile & 15) * 64;
        const int n0 = (tile >> 4) * 32;
        const int tx = tid & 31, ty = tid >> 5;     // 32 x 8
#pragma unroll
        for (int j = 0; j < 8; j++)
            t[ty * 8 + j][tx] = W[(size_t)(k0 + ty * 8 + j) * N + n0 + tx];
        __syncthreads();
#pragma unroll
        for (int j = 0; j < 4; j++) {
            const int n = ty + j * 8;
            __half2 v = __halves2half2(__float2half_rn(t[tx * 2][n]),
                                       __float2half_rn(t[tx * 2 + 1][n]));
            *reinterpret_cast<__half2*>(&T[(size_t)(n0 + n) * HID + k0 + tx * 2]) = v;
        }
    }
}

// ---------------------------------------------------------------------------
// Masked softmax: fp16 logits -> fp32 probabilities (mask via base-4 digits)
// ---------------------------------------------------------------------------
__global__ __launch_bounds__(256)
void masked_softmax_h(const __half* __restrict__ lg, float* __restrict__ out,
                      const float* __restrict__ states)
{
    const int row = blockIdx.x;
    const int tid = threadIdx.x;

    __shared__ float sred[32];
    __shared__ int scap[6];

    if (tid < 6) scap[tid] = (int)floorf(states[(size_t)row * SDIM + NS + tid]);
    __syncthreads();

    const int c0 = scap[0], c1 = scap[1], c2 = scap[2];
    const int c3 = scap[3], c4 = scap[4], c5 = scap[5];

    const __half* rowp = lg + (size_t)row * NACT;
    float* outp = out + (size_t)row * NACT;
    const int base = tid * 16;

    float vals[16];
    float mx = -INFINITY;

#pragma unroll
    for (int h = 0; h < 8; h++) {
        float2 f = __half22float2(reinterpret_cast<const __half2*>(rowp + base)[h]);
        vals[2 * h]     = f.x;
        vals[2 * h + 1] = f.y;
    }
#pragma unroll
    for (int c = 0; c < 16; c++) {
        const int a = base + c;
        bool feas = (((a >> 10) & 3) <= c0) && (((a >> 8) & 3) <= c1) &&
                    (((a >> 6)  & 3) <= c2) && (((a >> 4) & 3) <= c3) &&
                    (((a >> 2)  & 3) <= c4) && (((a)      & 3) <= c5);
        if (!feas) vals[c] += LOG_EPS;
        mx = fmaxf(mx, vals[c]);
    }

#pragma unroll
    for (int o = 16; o > 0; o >>= 1) mx = fmaxf(mx, __shfl_xor_sync(0xffffffffu, mx, o));
    if ((tid & 31) == 0) sred[tid >> 5] = mx;
    __syncthreads();
    if (tid < 32) {
        float m = (tid < 8) ? sred[tid] : -INFINITY;
#pragma unroll
        for (int o = 4; o > 0; o >>= 1) m = fmaxf(m, __shfl_xor_sync(0xffffffffu, m, o));
        if (tid == 0) sred[0] = m;
    }
    __syncthreads();
    mx = sred[0];
    __syncthreads();

    float sum = 0.0f;
#pragma unroll
    for (int i = 0; i < 16; i++) { vals[i] = expf(vals[i] - mx); sum += vals[i]; }

#pragma unroll
    for (int o = 16; o > 0; o >>= 1) sum += __shfl_xor_sync(0xffffffffu, sum, o);
    if ((tid & 31) == 0) sred[tid >> 5] = sum;
    __syncthreads();
    if (tid < 32) {
        float s = (tid < 8) ? sred[tid] : 0.0f;
#pragma unroll
        for (int o = 4; o > 0; o >>= 1) s += __shfl_xor_sync(0xffffffffu, s, o);
        if (tid == 0) sred[0] = s;
    }
    __syncthreads();
    const float inv = 1.0f / sred[0];

#pragma unroll
    for (int v4i = 0; v4i < 4; v4i++) {
        float4 o4;
        o4.x = vals[v4i * 4 + 0] * inv;
        o4.y = vals[v4i * 4 + 1] * inv;
        o4.z = vals[v4i * 4 + 2] * inv;
        o4.w = vals[v4i * 4 + 3] * inv;
        *reinterpret_cast<float4*>(outp + base + v4i * 4) = o4;
    }
}

// ---------------------------------------------------------------------------
extern "C" void kernel_launch(void* const* d_in, const int* in_sizes, int n_in,
                              void* d_out, int out_size)
{
    const float* states = (const float*)d_in[0];
    const float* W1     = (const float*)d_in[1];
    const float* b1     = (const float*)d_in[2];
    const float* W2     = (const float*)d_in[3];
    const float* b2     = (const float*)d_in[4];
    const float* Wh     = (const float*)d_in[5];
    const float* bh     = (const float*)d_in[6];
    float* out = (float*)d_out;

    __half *sp, *W1T, *h1, *h2, *W2T, *WhT, *lg;
    cudaGetSymbolAddress((void**)&sp,  g_sp);
    cudaGetSymbolAddress((void**)&W1T, g_W1T);
    cudaGetSymbolAddress((void**)&h1,  g_h1);
    cudaGetSymbolAddress((void**)&h2,  g_h2);
    cudaGetSymbolAddress((void**)&W2T, g_W2T);
    cudaGetSymbolAddress((void**)&WhT, g_WhT);
    cudaGetSymbolAddress((void**)&lg,  g_lg);

    cudaFuncSetAttribute((const void*)hmma_gemm<1, 2>,
                         cudaFuncAttributeMaxDynamicSharedMemorySize, HMMA_SMEM);
    cudaFuncSetAttribute((const void*)hmma_gemm<1, 16>,
                         cudaFuncAttributeMaxDynamicSharedMemorySize, HMMA_SMEM);
    cudaFuncSetAttribute((const void*)hmma_gemm<0, 16>,
                         cudaFuncAttributeMaxDynamicSharedMemorySize, HMMA_SMEM);

    // fused prep: pad states + W1^T, transpose W2/Wh to fp16 K-major
    prep_all<<<PREP_BLOCKS, 256>>>(states, W1, W2, Wh, sp, W1T, W2T, WhT);

    // layer 1 (HMMA, K=128 padded) -> h1 fp16
    hmma_gemm<1, 2><<<dim3(HID / 128, BATCH / 128), 256, HMMA_SMEM>>>(
        sp, W1T, b1, h1, HID);
    // layer 2 (HMMA) -> h2 fp16
    hmma_gemm<1, 16><<<dim3(HID / 128, BATCH / 128), 256, HMMA_SMEM>>>(
        h1, W2T, b2, h2, HID);
    // head (HMMA) -> plain fp16 logits
    hmma_gemm<0, 16><<<dim3(NACT / 128, BATCH / 128), 256, HMMA_SMEM>>>(
        h2, WhT, bh, lg, NACT);
    // masked softmax: fp16 logits + states -> fp32 probabilities
    masked_softmax_h<<<BATCH, 256>>>(lg, out, states);
}

// round 14
// speedup vs baseline: 1.0537x; 1.0101x over previous
#include <cuda_runtime.h>
#include <cuda_fp16.h>
#include <math.h>
#include <stdint.h>

// Problem constants
#define BATCH 8192
#define SDIM  70
#define NS    64
#define HID   1024
#define NACT  4096
#define K1PAD 128                        // K=70 zero-padded for HMMA layer 1
#define LOG_EPS (-20.723265836946407f)   // logf(1e-9f)

// PDL helpers (sm_90+; sm_103 qualifies)
#if defined(__CUDA_ARCH__) && (__CUDA_ARCH__ >= 900)
#define PDL_WAIT()    cudaGridDependencySynchronize()
#define PDL_TRIGGER() cudaTriggerProgrammaticLaunchCompletion()
#else
#define PDL_WAIT()
#define PDL_TRIGGER()
#endif

// ---------------------------------------------------------------------------
// Scratch (allocation-free __device__ globals)
// ---------------------------------------------------------------------------
__device__ __align__(16) __half g_sp[BATCH * K1PAD];    // states fp16, K-padded
__device__ __align__(16) __half g_W1T[HID * K1PAD];     // W1^T fp16, K-padded
__device__ __align__(16) __half g_h1[BATCH * HID];
__device__ __align__(16) __half g_h2[BATCH * HID];
__device__ __align__(16) __half g_W2T[HID * HID];
__device__ __align__(16) __half g_WhT[NACT * HID];
__device__ __align__(16) __half g_lg[BATCH * NACT];     // fp16 logits (unmasked)

// ---------------------------------------------------------------------------
// Helpers (plain sm_80+ PTX only — nothing sm_103a-conditional)
// ---------------------------------------------------------------------------
__device__ __forceinline__ uint32_t smem_u32(const void* p) {
    uint32_t a;
    asm("{ .reg .u64 t; cvta.to.shared.u64 t, %1; cvt.u32.u64 %0, t; }" : "=r"(a) : "l"(p));
    return a;
}

__device__ __forceinline__ void cp_async16(uint32_t saddr, const void* gaddr) {
    asm volatile("cp.async.cg.shared.global [%0], [%1], 16;" :: "r"(saddr), "l"(gaddr));
}
#define CP_COMMIT()  asm volatile("cp.async.commit_group;" ::: "memory")
#define CP_WAIT(n)   asm volatile("cp.async.wait_group %0;" :: "n"(n) : "memory")

__device__ __forceinline__ void ldsm_x4(uint32_t* r, uint32_t addr) {
    asm volatile("ldmatrix.sync.aligned.m8n8.x4.shared.b16 {%0,%1,%2,%3}, [%4];"
        : "=r"(r[0]), "=r"(r[1]), "=r"(r[2]), "=r"(r[3]) : "r"(addr));
}

__device__ __forceinline__ void mma16816(float* d, const uint32_t* a, const uint32_t* b) {
    asm volatile("mma.sync.aligned.m16n8k16.row.col.f32.f16.f16.f32 "
        "{%0,%1,%2,%3}, {%4,%5,%6,%7}, {%8,%9}, {%0,%1,%2,%3};"
        : "+f"(d[0]), "+f"(d[1]), "+f"(d[2]), "+f"(d[3])
        : "r"(a[0]), "r"(a[1]), "r"(a[2]), "r"(a[3]), "r"(b[0]), "r"(b[1]));
}

// ---------------------------------------------------------------------------
// HMMA GEMM (single fp16) — R11/R13-proven configuration, locked:
//   OUT==0: Ch = (A @ B^T + bias) as fp16  (plain logits)
//   OUT==1: Ch = tanh(A @ B^T + bias) as fp16
// CTA tile 128x128, 256 threads, 8 warps in 4(m) x 2(n); warp tile 32 x 64.
// 3-stage cp.async ring, ONE __syncthreads per K-tile, fully unrolled.
// XOR-8 swizzled 128B smem rows. 2 CTAs/SM. PDL wait before first load,
// PDL trigger after last store.
// ---------------------------------------------------------------------------
#define KT 64
#define A_BYTES  16384                 // 128 rows x 128 B
#define STAGE_BYTES (2 * A_BYTES)      // A + B = 32768
#define NSTAGE 3
#define HMMA_SMEM (NSTAGE * STAGE_BYTES)   // 98304

template <int OUT, int NST>
__global__ __launch_bounds__(256, 2)
void hmma_gemm(const __half* __restrict__ A, const __half* __restrict__ B,
               const float* __restrict__ bias,
               __half* __restrict__ Ch, int Ntot)
{
    constexpr int K = NST * KT;
    extern __shared__ char smem_raw[];
    const uint32_t sbase = smem_u32(smem_raw);

    const int tid  = threadIdx.x;
    const int lane = tid & 31;
    const int wid  = tid >> 5;
    const int wm   = wid & 3;          // 4 warps along M (32 rows each)
    const int wn   = wid >> 2;         // 2 warps along N (64 cols each)
    const int bm   = blockIdx.y * 128;
    const int bn   = blockIdx.x * 128;

    float acc[2][8][4];
#pragma unroll
    for (int i = 0; i < 2; i++)
#pragma unroll
        for (int j = 0; j < 8; j++)
#pragma unroll
            for (int q = 0; q < 4; q++) acc[i][j][q] = 0.0f;

    // ---- stage loader: 2 x 1024 16B chunks (A, B), 8 per thread -------------
    auto load_stage = [&](int i, int s) {
        const int kl = i * KT;
        const uint32_t sA = sbase + s * STAGE_BYTES;
        const uint32_t sB = sA + A_BYTES;
#pragma unroll
        for (int p = 0; p < 4; p++) {
            const int idx = p * 256 + tid;
            const int r = idx >> 3, c = idx & 7;
            const uint32_t so = r * 128 + ((c ^ (r & 7)) << 4);
            cp_async16(sA + so, A + (size_t)(bm + r) * K + kl + c * 8);
            cp_async16(sB + so, B + (size_t)(bn + r) * K + kl + c * 8);
        }
        CP_COMMIT();
    };

    PDL_WAIT();                         // producer output must be visible

    load_stage(0, 0);
    if (NST > 1) load_stage(1, 1);

#pragma unroll
    for (int i = 0; i < NST; i++) {
        const int s = i % NSTAGE;
        if (i + 1 < NST) { CP_WAIT(1); } else { CP_WAIT(0); }
        __syncthreads();

        // refill the slot drained at iter i-1 (stage i+2 -> slot (i+2)%3)
        if (i + 2 < NST) load_stage(i + 2, (i + 2) % NSTAGE);

        const uint32_t sA = sbase + s * STAGE_BYTES;
        const uint32_t sB = sA + A_BYTES;

#pragma unroll
        for (int ks = 0; ks < KT / 16; ks++) {
            // A fragments: 2 m16 tiles
            uint32_t a[2][4];
#pragma unroll
            for (int mt = 0; mt < 2; mt++) {
                const int row = wm * 32 + mt * 16 + (lane & 15);
                const int ch  = ks * 2 + (lane >> 4);
                ldsm_x4(a[mt], sA + row * 128 + ((ch ^ (row & 7)) << 4));
            }
            // B fragments: 4 x ldmatrix.x4
            uint32_t b[4][4];
#pragma unroll
            for (int np = 0; np < 4; np++) {
                const int nrow = wn * 64 + np * 16 + ((lane >> 4) << 3) + (lane & 7);
                const int ch   = ks * 2 + ((lane >> 3) & 1);
                ldsm_x4(b[np], sB + nrow * 128 + ((ch ^ (nrow & 7)) << 4));
            }
#pragma unroll
            for (int mt = 0; mt < 2; mt++)
#pragma unroll
                for (int np = 0; np < 4; np++) {
                    mma16816(acc[mt][np * 2 + 0], a[mt], &b[np][0]);
                    mma16816(acc[mt][np * 2 + 1], a[mt], &b[np][2]);
                }
        }
    }

    // ---- epilogue ----
    const int q  = lane & 3;
    const int r4 = lane >> 2;
#pragma unroll
    for (int mt = 0; mt < 2; mt++) {
#pragma unroll
        for (int nt = 0; nt < 8; nt++) {
            const int row0 = bm + wm * 32 + mt * 16 + r4;
            const int col  = bn + wn * 64 + nt * 8 + q * 2;
            const float b0 = bias[col], b1 = bias[col + 1];
            float d0 = acc[mt][nt][0] + b0;
            float d1 = acc[mt][nt][1] + b1;
            float d2 = acc[mt][nt][2] + b0;
            float d3 = acc[mt][nt][3] + b1;
            if (OUT == 1) {
                d0 = tanhf(d0); d1 = tanhf(d1); d2 = tanhf(d2); d3 = tanhf(d3);
            }
            *reinterpret_cast<__half2*>(Ch + (size_t)row0 * Ntot + col) =
                __halves2half2(__float2half_rn(d0), __float2half_rn(d1));
            *reinterpret_cast<__half2*>(Ch + (size_t)(row0 + 8) * Ntot + col) =
                __halves2half2(__float2half_rn(d2), __float2half_rn(d3));
        }
    }
    PDL_TRIGGER();                      // allow dependent grid to spin up
}

// ---------------------------------------------------------------------------
// Fused prep: one grid, block-range dispatch.
//   [0, 4096)        pad states -> g_sp
//   [4096, 4608)     pad W1^T   -> g_W1T
//   [4608, 5120)     transpose W2 (16 k-tiles x 32 n-tiles)
//   [5120, 7168)     transpose Wh (16 k-tiles x 128 n-tiles)
// ---------------------------------------------------------------------------
#define PREP_BLOCKS 7168

__global__ __launch_bounds__(256)
void prep_all(const float* __restrict__ S,  const float* __restrict__ W1,
              const float* __restrict__ W2, const float* __restrict__ Wh,
              __half* __restrict__ sp, __half* __restrict__ W1T,
              __half* __restrict__ W2T, __half* __restrict__ WhT)
{
    __shared__ float t[64][33];
    const int blk = blockIdx.x;
    const int tid = threadIdx.x;

    if (blk < 4096) {
        // pad states
        const int idx = blk * 256 + tid;
        const int m = idx >> 7, k = idx & 127;
        sp[idx] = (k < SDIM) ? __float2half_rn(S[(size_t)m * SDIM + k]) : __half(0.0f);
    } else if (blk < 4608) {
        // pad W1^T
        const int idx = (blk - 4096) * 256 + tid;
        const int n = idx >> 7, k = idx & 127;
        W1T[idx] = (k < SDIM) ? __float2half_rn(W1[(size_t)k * HID + n]) : __half(0.0f);
    } else {
        // transpose: W[K=1024, N] -> T[N, 1024]; 64(k) x 32(n) tiles
        const float* W; __half* T; int N, tile;
        if (blk < 5120) { W = W2; T = W2T; N = HID;  tile = blk - 4608; }
        else            { W = Wh; T = WhT; N = NACT; tile = blk - 5120; }
        const int k0 = (tile & 15) * 64;
        const int n0 = (tile >> 4) * 32;
        const int tx = tid & 31, ty = tid >> 5;     // 32 x 8
#pragma unroll
        for (int j = 0; j < 8; j++)
            t[ty * 8 + j][tx] = W[(size_t)(k0 + ty * 8 + j) * N + n0 + tx];
        __syncthreads();
#pragma unroll
        for (int j = 0; j < 4; j++) {
            const int n = ty + j * 8;
            __half2 v = __halves2half2(__float2half_rn(t[tx * 2][n]),
                                       __float2half_rn(t[tx * 2 + 1][n]));
            *reinterpret_cast<__half2*>(&T[(size_t)(n0 + n) * HID + k0 + tx * 2]) = v;
        }
    }
    PDL_TRIGGER();
}

// ---------------------------------------------------------------------------
// Masked softmax: fp16 logits -> fp32 probabilities (mask via base-4 digits)
// ---------------------------------------------------------------------------
__global__ __launch_bounds__(256)
void masked_softmax_h(const __half* __restrict__ lg, float* __restrict__ out,
                      const float* __restrict__ states)
{
    const int row = blockIdx.x;
    const int tid = threadIdx.x;

    __shared__ float sred[32];
    __shared__ int scap[6];

    PDL_WAIT();

    if (tid < 6) scap[tid] = (int)floorf(states[(size_t)row * SDIM + NS + tid]);
    __syncthreads();

    const int c0 = scap[0], c1 = scap[1], c2 = scap[2];
    const int c3 = scap[3], c4 = scap[4], c5 = scap[5];

    const __half* rowp = lg + (size_t)row * NACT;
    float* outp = out + (size_t)row * NACT;
    const int base = tid * 16;

    float vals[16];
    float mx = -INFINITY;

#pragma unroll
    for (int h = 0; h < 8; h++) {
        float2 f = __half22float2(reinterpret_cast<const __half2*>(rowp + base)[h]);
        vals[2 * h]     = f.x;
        vals[2 * h + 1] = f.y;
    }
#pragma unroll
    for (int c = 0; c < 16; c++) {
        const int a = base + c;
        bool feas = (((a >> 10) & 3) <= c0) && (((a >> 8) & 3) <= c1) &&
                    (((a >> 6)  & 3) <= c2) && (((a >> 4) & 3) <= c3) &&
                    (((a >> 2)  & 3) <= c4) && (((a)      & 3) <= c5);
        if (!feas) vals[c] += LOG_EPS;
        mx = fmaxf(mx, vals[c]);
    }

#pragma unroll
    for (int o = 16; o > 0; o >>= 1) mx = fmaxf(mx, __shfl_xor_sync(0xffffffffu, mx, o));
    if ((tid & 31) == 0) sred[tid >> 5] = mx;
    __syncthreads();
    if (tid < 32) {
        float m = (tid < 8) ? sred[tid] : -INFINITY;
#pragma unroll
        for (int o = 4; o > 0; o >>= 1) m = fmaxf(m, __shfl_xor_sync(0xffffffffu, m, o));
        if (tid == 0) sred[0] = m;
    }
    __syncthreads();
    mx = sred[0];
    __syncthreads();

    float sum = 0.0f;
#pragma unroll
    for (int i = 0; i < 16; i++) { vals[i] = expf(vals[i] - mx); sum += vals[i]; }

#pragma unroll
    for (int o = 16; o > 0; o >>= 1) sum += __shfl_xor_sync(0xffffffffu, sum, o);
    if ((tid & 31) == 0) sred[tid >> 5] = sum;
    __syncthreads();
    if (tid < 32) {
        float s = (tid < 8) ? sred[tid] : 0.0f;
#pragma unroll
        for (int o = 4; o > 0; o >>= 1) s += __shfl_xor_sync(0xffffffffu, s, o);
        if (tid == 0) sred[0] = s;
    }
    __syncthreads();
    const float inv = 1.0f / sred[0];

#pragma unroll
    for (int v4i = 0; v4i < 4; v4i++) {
        float4 o4;
        o4.x = vals[v4i * 4 + 0] * inv;
        o4.y = vals[v4i * 4 + 1] * inv;
        o4.z = vals[v4i * 4 + 2] * inv;
        o4.w = vals[v4i * 4 + 3] * inv;
        *reinterpret_cast<float4*>(outp + base + v4i * 4) = o4;
    }
}

// ---------------------------------------------------------------------------
// Host-side PDL launch helper
// ---------------------------------------------------------------------------
template <typename F, typename... Args>
static void launch_pdl(F* func, dim3 grid, dim3 block, size_t smem, Args... args)
{
    cudaLaunchConfig_t cfg = {};
    cfg.gridDim = grid;
    cfg.blockDim = block;
    cfg.dynamicSmemBytes = smem;
    cfg.stream = 0;
    cudaLaunchAttribute attr[1];
    attr[0].id = cudaLaunchAttributeProgrammaticStreamSerialization;
    attr[0].val.programmaticStreamSerializationAllowed = 1;
    cfg.attrs = attr;
    cfg.numAttrs = 1;
    cudaLaunchKernelEx(&cfg, func, args...);
}

// ---------------------------------------------------------------------------
extern "C" void kernel_launch(void* const* d_in, const int* in_sizes, int n_in,
                              void* d_out, int out_size)
{
    const float* states = (const float*)d_in[0];
    const float* W1     = (const float*)d_in[1];
    const float* b1     = (const float*)d_in[2];
    const float* W2     = (const float*)d_in[3];
    const float* b2     = (const float*)d_in[4];
    const float* Wh     = (const float*)d_in[5];
    const float* bh     = (const float*)d_in[6];
    float* out = (float*)d_out;

    __half *sp, *W1T, *h1, *h2, *W2T, *WhT, *lg;
    cudaGetSymbolAddress((void**)&sp,  g_sp);
    cudaGetSymbolAddress((void**)&W1T, g_W1T);
    cudaGetSymbolAddress((void**)&h1,  g_h1);
    cudaGetSymbolAddress((void**)&h2,  g_h2);
    cudaGetSymbolAddress((void**)&W2T, g_W2T);
    cudaGetSymbolAddress((void**)&WhT, g_WhT);
    cudaGetSymbolAddress((void**)&lg,  g_lg);

    cudaFuncSetAttribute((const void*)hmma_gemm<1, 2>,
                         cudaFuncAttributeMaxDynamicSharedMemorySize, HMMA_SMEM);
    cudaFuncSetAttribute((const void*)hmma_gemm<1, 16>,
                         cudaFuncAttributeMaxDynamicSharedMemorySize, HMMA_SMEM);
    cudaFuncSetAttribute((const void*)hmma_gemm<0, 16>,
                         cudaFuncAttributeMaxDynamicSharedMemorySize, HMMA_SMEM);

    // fused prep: pad states + W1^T, transpose W2/Wh to fp16 K-major
    prep_all<<<PREP_BLOCKS, 256>>>(states, W1, W2, Wh, sp, W1T, W2T, WhT);

    // layer 1 (HMMA, K=128 padded) -> h1 fp16        [PDL on prep]
    launch_pdl(hmma_gemm<1, 2>, dim3(HID / 128, BATCH / 128), dim3(256), HMMA_SMEM,
               (const __half*)sp, (const __half*)W1T, b1, h1, HID);
    // layer 2 (HMMA) -> h2 fp16                      [PDL on layer 1]
    launch_pdl(hmma_gemm<1, 16>, dim3(HID / 128, BATCH / 128), dim3(256), HMMA_SMEM,
               (const __half*)h1, (const __half*)W2T, b2, h2, HID);
    // head (HMMA) -> plain fp16 logits               [PDL on layer 2]
    launch_pdl(hmma_gemm<0, 16>, dim3(NACT / 128, BATCH / 128), dim3(256), HMMA_SMEM,
               (const __half*)h2, (const __half*)WhT, bh, lg, NACT);
    // masked softmax -> fp32 probabilities           [PDL on head]
    launch_pdl(masked_softmax_h, dim3(BATCH), dim3(256), (size_t)0,
               (const __half*)lg, out, states);
}

// round 15
// speedup vs baseline: 1.0686x; 1.0141x over previous
#include <cuda_runtime.h>
#include <cuda_fp16.h>
#include <math.h>
#include <stdint.h>

// Problem constants
#define BATCH 8192
#define SDIM  70
#define NS    64
#define HID   1024
#define NACT  4096
#define K1PAD 128                        // K=70 zero-padded for HMMA layer 1
#define LOG_EPS (-20.723265836946407f)   // logf(1e-9f)

// PDL helpers (sm_90+; sm_103 qualifies)
#if defined(__CUDA_ARCH__) && (__CUDA_ARCH__ >= 900)
#define PDL_WAIT()    cudaGridDependencySynchronize()
#define PDL_TRIGGER() cudaTriggerProgrammaticLaunchCompletion()
#else
#define PDL_WAIT()
#define PDL_TRIGGER()
#endif

// ---------------------------------------------------------------------------
// Scratch (allocation-free __device__ globals)
// ---------------------------------------------------------------------------
__device__ __align__(16) __half g_sp[BATCH * K1PAD];    // states fp16, K-padded
__device__ __align__(16) __half g_W1T[HID * K1PAD];     // W1^T fp16, K-padded
__device__ __align__(16) __half g_h1[BATCH * HID];
__device__ __align__(16) __half g_h2[BATCH * HID];
__device__ __align__(16) __half g_W2T[HID * HID];
__device__ __align__(16) __half g_WhT[NACT * HID];
__device__ __align__(16) __half g_lg[BATCH * NACT];     // fp16 logits (unmasked)

// ---------------------------------------------------------------------------
// Helpers (plain sm_80+ PTX only — nothing sm_103a-conditional)
// ---------------------------------------------------------------------------
__device__ __forceinline__ uint32_t smem_u32(const void* p) {
    uint32_t a;
    asm("{ .reg .u64 t; cvta.to.shared.u64 t, %1; cvt.u32.u64 %0, t; }" : "=r"(a) : "l"(p));
    return a;
}

__device__ __forceinline__ void cp_async16(uint32_t saddr, const void* gaddr) {
    asm volatile("cp.async.cg.shared.global [%0], [%1], 16;" :: "r"(saddr), "l"(gaddr));
}
#define CP_COMMIT()  asm volatile("cp.async.commit_group;" ::: "memory")
#define CP_WAIT(n)   asm volatile("cp.async.wait_group %0;" :: "n"(n) : "memory")

__device__ __forceinline__ void ldsm_x4(uint32_t* r, uint32_t addr) {
    asm volatile("ldmatrix.sync.aligned.m8n8.x4.shared.b16 {%0,%1,%2,%3}, [%4];"
        : "=r"(r[0]), "=r"(r[1]), "=r"(r[2]), "=r"(r[3]) : "r"(addr));
}

__device__ __forceinline__ void mma16816(float* d, const uint32_t* a, const uint32_t* b) {
    asm volatile("mma.sync.aligned.m16n8k16.row.col.f32.f16.f16.f32 "
        "{%0,%1,%2,%3}, {%4,%5,%6,%7}, {%8,%9}, {%0,%1,%2,%3};"
        : "+f"(d[0]), "+f"(d[1]), "+f"(d[2]), "+f"(d[3])
        : "r"(a[0]), "r"(a[1]), "r"(a[2]), "r"(a[3]), "r"(b[0]), "r"(b[1]));
}

// ---------------------------------------------------------------------------
// HMMA GEMM (single fp16) — R11/R13-proven configuration, LOCKED:
//   OUT==0: Ch = (A @ B^T + bias) as fp16  (plain logits)
//   OUT==1: Ch = tanh(A @ B^T + bias) as fp16
// CTA tile 128x128, 256 threads, 8 warps in 4(m) x 2(n); warp tile 32 x 64.
// 3-stage cp.async ring, ONE __syncthreads per K-tile, fully unrolled.
// XOR-8 swizzled 128B smem rows. 2 CTAs/SM. PDL wait/trigger.
// ---------------------------------------------------------------------------
#define KT 64
#define A_BYTES  16384                 // 128 rows x 128 B
#define STAGE_BYTES (2 * A_BYTES)      // A + B = 32768
#define NSTAGE 3
#define HMMA_SMEM (NSTAGE * STAGE_BYTES)   // 98304

template <int OUT, int NST>
__global__ __launch_bounds__(256, 2)
void hmma_gemm(const __half* __restrict__ A, const __half* __restrict__ B,
               const float* __restrict__ bias,
               __half* __restrict__ Ch, int Ntot)
{
    constexpr int K = NST * KT;
    extern __shared__ char smem_raw[];
    const uint32_t sbase = smem_u32(smem_raw);

    const int tid  = threadIdx.x;
    const int lane = tid & 31;
    const int wid  = tid >> 5;
    const int wm   = wid & 3;          // 4 warps along M (32 rows each)
    const int wn   = wid >> 2;         // 2 warps along N (64 cols each)
    const int bm   = blockIdx.y * 128;
    const int bn   = blockIdx.x * 128;

    float acc[2][8][4];
#pragma unroll
    for (int i = 0; i < 2; i++)
#pragma unroll
        for (int j = 0; j < 8; j++)
#pragma unroll
            for (int q = 0; q < 4; q++) acc[i][j][q] = 0.0f;

    // ---- stage loader: 2 x 1024 16B chunks (A, B), 8 per thread -------------
    auto load_stage = [&](int i, int s) {
        const int kl = i * KT;
        const uint32_t sA = sbase + s * STAGE_BYTES;
        const uint32_t sB = sA + A_BYTES;
#pragma unroll
        for (int p = 0; p < 4; p++) {
            const int idx = p * 256 + tid;
            const int r = idx >> 3, c = idx & 7;
            const uint32_t so = r * 128 + ((c ^ (r & 7)) << 4);
            cp_async16(sA + so, A + (size_t)(bm + r) * K + kl + c * 8);
            cp_async16(sB + so, B + (size_t)(bn + r) * K + kl + c * 8);
        }
        CP_COMMIT();
    };

    PDL_WAIT();                         // producer output must be visible

    load_stage(0, 0);
    if (NST > 1) load_stage(1, 1);

#pragma unroll
    for (int i = 0; i < NST; i++) {
        const int s = i % NSTAGE;
        if (i + 1 < NST) { CP_WAIT(1); } else { CP_WAIT(0); }
        __syncthreads();

        // refill the slot drained at iter i-1 (stage i+2 -> slot (i+2)%3)
        if (i + 2 < NST) load_stage(i + 2, (i + 2) % NSTAGE);

        const uint32_t sA = sbase + s * STAGE_BYTES;
        const uint32_t sB = sA + A_BYTES;

#pragma unroll
        for (int ks = 0; ks < KT / 16; ks++) {
            // A fragments: 2 m16 tiles
            uint32_t a[2][4];
#pragma unroll
            for (int mt = 0; mt < 2; mt++) {
                const int row = wm * 32 + mt * 16 + (lane & 15);
                const int ch  = ks * 2 + (lane >> 4);
                ldsm_x4(a[mt], sA + row * 128 + ((ch ^ (row & 7)) << 4));
            }
            // B fragments: 4 x ldmatrix.x4
            uint32_t b[4][4];
#pragma unroll
            for (int np = 0; np < 4; np++) {
                const int nrow = wn * 64 + np * 16 + ((lane >> 4) << 3) + (lane & 7);
                const int ch   = ks * 2 + ((lane >> 3) & 1);
                ldsm_x4(b[np], sB + nrow * 128 + ((ch ^ (nrow & 7)) << 4));
            }
#pragma unroll
            for (int mt = 0; mt < 2; mt++)
#pragma unroll
                for (int np = 0; np < 4; np++) {
                    mma16816(acc[mt][np * 2 + 0], a[mt], &b[np][0]);
                    mma16816(acc[mt][np * 2 + 1], a[mt], &b[np][2]);
                }
        }
    }

    // ---- epilogue ----
    const int q  = lane & 3;
    const int r4 = lane >> 2;
#pragma unroll
    for (int mt = 0; mt < 2; mt++) {
#pragma unroll
        for (int nt = 0; nt < 8; nt++) {
            const int row0 = bm + wm * 32 + mt * 16 + r4;
            const int col  = bn + wn * 64 + nt * 8 + q * 2;
            const float b0 = bias[col], b1 = bias[col + 1];
            float d0 = acc[mt][nt][0] + b0;
            float d1 = acc[mt][nt][1] + b1;
            float d2 = acc[mt][nt][2] + b0;
            float d3 = acc[mt][nt][3] + b1;
            if (OUT == 1) {
                d0 = tanhf(d0); d1 = tanhf(d1); d2 = tanhf(d2); d3 = tanhf(d3);
            }
            *reinterpret_cast<__half2*>(Ch + (size_t)row0 * Ntot + col) =
                __halves2half2(__float2half_rn(d0), __float2half_rn(d1));
            *reinterpret_cast<__half2*>(Ch + (size_t)(row0 + 8) * Ntot + col) =
                __halves2half2(__float2half_rn(d2), __float2half_rn(d3));
        }
    }
    PDL_TRIGGER();                      // allow dependent grid to spin up
}

// ---------------------------------------------------------------------------
// Fused prep: one grid, block-range dispatch.
//   [0, 4096)        pad states -> g_sp
//   [4096, 4608)     pad W1^T   -> g_W1T
//   [4608, 5120)     transpose W2 (16 k-tiles x 32 n-tiles)
//   [5120, 7168)     transpose Wh (16 k-tiles x 128 n-tiles)
// ---------------------------------------------------------------------------
#define PREP_BLOCKS 7168

__global__ __launch_bounds__(256)
void prep_all(const float* __restrict__ S,  const float* __restrict__ W1,
              const float* __restrict__ W2, const float* __restrict__ Wh,
              __half* __restrict__ sp, __half* __restrict__ W1T,
              __half* __restrict__ W2T, __half* __restrict__ WhT)
{
    __shared__ float t[64][33];
    const int blk = blockIdx.x;
    const int tid = threadIdx.x;

    if (blk < 4096) {
        // pad states
        const int idx = blk * 256 + tid;
        const int m = idx >> 7, k = idx & 127;
        sp[idx] = (k < SDIM) ? __float2half_rn(S[(size_t)m * SDIM + k]) : __half(0.0f);
    } else if (blk < 4608) {
        // pad W1^T
        const int idx = (blk - 4096) * 256 + tid;
        const int n = idx >> 7, k = idx & 127;
        W1T[idx] = (k < SDIM) ? __float2half_rn(W1[(size_t)k * HID + n]) : __half(0.0f);
    } else {
        // transpose: W[K=1024, N] -> T[N, 1024]; 64(k) x 32(n) tiles
        const float* W; __half* T; int N, tile;
        if (blk < 5120) { W = W2; T = W2T; N = HID;  tile = blk - 4608; }
        else            { W = Wh; T = WhT; N = NACT; tile = blk - 5120; }
        const int k0 = (tile & 15) * 64;
        const int n0 = (tile >> 4) * 32;
        const int tx = tid & 31, ty = tid >> 5;     // 32 x 8
#pragma unroll
        for (int j = 0; j < 8; j++)
            t[ty * 8 + j][tx] = W[(size_t)(k0 + ty * 8 + j) * N + n0 + tx];
        __syncthreads();
#pragma unroll
        for (int j = 0; j < 4; j++) {
            const int n = ty + j * 8;
            __half2 v = __halves2half2(__float2half_rn(t[tx * 2][n]),
                                       __float2half_rn(t[tx * 2 + 1][n]));
            *reinterpret_cast<__half2*>(&T[(size_t)(n0 + n) * HID + k0 + tx * 2]) = v;
        }
    }
    PDL_TRIGGER();
}

// ---------------------------------------------------------------------------
// Masked softmax: fp16 logits -> fp32 probabilities.
// Per-thread base = tid*16 fixes the top 4 base-4 digits -> single hoisted
// `fixed` predicate; only digits 4,5 tested per element. __expf for the exp.
// ---------------------------------------------------------------------------
__global__ __launch_bounds__(256)
void masked_softmax_h(const __half* __restrict__ lg, float* __restrict__ out,
                      const float* __restrict__ states)
{
    const int row = blockIdx.x;
    const int tid = threadIdx.x;

    __shared__ float sred[32];
    __shared__ int scap[6];

    PDL_WAIT();

    if (tid < 6) scap[tid] = (int)floorf(states[(size_t)row * SDIM + NS + tid]);
    __syncthreads();

    const int c0 = scap[0], c1 = scap[1], c2 = scap[2];
    const int c3 = scap[3], c4 = scap[4], c5 = scap[5];

    const __half* rowp = lg + (size_t)row * NACT;
    float* outp = out + (size_t)row * NACT;
    const int base = tid * 16;

    // top-4 digits constant across this thread's 16 consecutive actions
    const bool fixed = (((base >> 10) & 3) <= c0) && (((base >> 8) & 3) <= c1) &&
                       (((base >> 6)  & 3) <= c2) && (((base >> 4) & 3) <= c3);

    float vals[16];
    float mx = -INFINITY;

#pragma unroll
    for (int h = 0; h < 8; h++) {
        float2 f = __half22float2(reinterpret_cast<const __half2*>(rowp + base)[h]);
        vals[2 * h]     = f.x;
        vals[2 * h + 1] = f.y;
    }
#pragma unroll
    for (int i = 0; i < 16; i++) {
        const bool feas = fixed && ((i >> 2) <= c4) && ((i & 3) <= c5);
        if (!feas) vals[i] += LOG_EPS;
        mx = fmaxf(mx, vals[i]);
    }

#pragma unroll
    for (int o = 16; o > 0; o >>= 1) mx = fmaxf(mx, __shfl_xor_sync(0xffffffffu, mx, o));
    if ((tid & 31) == 0) sred[tid >> 5] = mx;
    __syncthreads();
    if (tid < 32) {
        float m = (tid < 8) ? sred[tid] : -INFINITY;
#pragma unroll
        for (int o = 4; o > 0; o >>= 1) m = fmaxf(m, __shfl_xor_sync(0xffffffffu, m, o));
        if (tid == 0) sred[0] = m;
    }
    __syncthreads();
    mx = sred[0];
    __syncthreads();

    float sum = 0.0f;
#pragma unroll
    for (int i = 0; i < 16; i++) { vals[i] = __expf(vals[i] - mx); sum += vals[i]; }

#pragma unroll
    for (int o = 16; o > 0; o >>= 1) sum += __shfl_xor_sync(0xffffffffu, sum, o);
    if ((tid & 31) == 0) sred[tid >> 5] = sum;
    __syncthreads();
    if (tid < 32) {
        float s = (tid < 8) ? sred[tid] : 0.0f;
#pragma unroll
        for (int o = 4; o > 0; o >>= 1) s += __shfl_xor_sync(0xffffffffu, s, o);
        if (tid == 0) sred[0] = s;
    }
    __syncthreads();
    const float inv = 1.0f / sred[0];

#pragma unroll
    for (int v4i = 0; v4i < 4; v4i++) {
        float4 o4;
        o4.x = vals[v4i * 4 + 0] * inv;
        o4.y = vals[v4i * 4 + 1] * inv;
        o4.z = vals[v4i * 4 + 2] * inv;
        o4.w = vals[v4i * 4 + 3] * inv;
        *reinterpret_cast<float4*>(outp + base + v4i * 4) = o4;
    }
}

// ---------------------------------------------------------------------------
// Host-side PDL launch helper
// ---------------------------------------------------------------------------
template <typename F, typename... Args>
static void launch_pdl(F* func, dim3 grid, dim3 block, size_t smem, Args... args)
{
    cudaLaunchConfig_t cfg = {};
    cfg.gridDim = grid;
    cfg.blockDim = block;
    cfg.dynamicSmemBytes = smem;
    cfg.stream = 0;
    cudaLaunchAttribute attr[1];
    attr[0].id = cudaLaunchAttributeProgrammaticStreamSerialization;
    attr[0].val.programmaticStreamSerializationAllowed = 1;
    cfg.attrs = attr;
    cfg.numAttrs = 1;
    cudaLaunchKernelEx(&cfg, func, args...);
}

// ---------------------------------------------------------------------------
extern "C" void kernel_launch(void* const* d_in, const int* in_sizes, int n_in,
                              void* d_out, int out_size)
{
    const float* states = (const float*)d_in[0];
    const float* W1     = (const float*)d_in[1];
    const float* b1     = (const float*)d_in[2];
    const float* W2     = (const float*)d_in[3];
    const float* b2     = (const float*)d_in[4];
    const float* Wh     = (const float*)d_in[5];
    const float* bh     = (const float*)d_in[6];
    float* out = (float*)d_out;

    __half *sp, *W1T, *h1, *h2, *W2T, *WhT, *lg;
    cudaGetSymbolAddress((void**)&sp,  g_sp);
    cudaGetSymbolAddress((void**)&W1T, g_W1T);
    cudaGetSymbolAddress((void**)&h1,  g_h1);
    cudaGetSymbolAddress((void**)&h2,  g_h2);
    cudaGetSymbolAddress((void**)&W2T, g_W2T);
    cudaGetSymbolAddress((void**)&WhT, g_WhT);
    cudaGetSymbolAddress((void**)&lg,  g_lg);

    cudaFuncSetAttribute((const void*)hmma_gemm<1, 2>,
                         cudaFuncAttributeMaxDynamicSharedMemorySize, HMMA_SMEM);
    cudaFuncSetAttribute((const void*)hmma_gemm<1, 16>,
                         cudaFuncAttributeMaxDynamicSharedMemorySize, HMMA_SMEM);
    cudaFuncSetAttribute((const void*)hmma_gemm<0, 16>,
                         cudaFuncAttributeMaxDynamicSharedMemorySize, HMMA_SMEM);

    // fused prep: pad states + W1^T, transpose W2/Wh to fp16 K-major
    prep_all<<<PREP_BLOCKS, 256>>>(states, W1, W2, Wh, sp, W1T, W2T, WhT);

    // layer 1 (HMMA, K=128 padded) -> h1 fp16        [PDL on prep]
    launch_pdl(hmma_gemm<1, 2>, dim3(HID / 128, BATCH / 128), dim3(256), HMMA_SMEM,
               (const __half*)sp, (const __half*)W1T, b1, h1, HID);
    // layer 2 (HMMA) -> h2 fp16                      [PDL on layer 1]
    launch_pdl(hmma_gemm<1, 16>, dim3(HID / 128, BATCH / 128), dim3(256), HMMA_SMEM,
               (const __half*)h1, (const __half*)W2T, b2, h2, HID);
    // head (HMMA) -> plain fp16 logits               [PDL on layer 2]
    launch_pdl(hmma_gemm<0, 16>, dim3(NACT / 128, BATCH / 128), dim3(256), HMMA_SMEM,
               (const __half*)h2, (const __half*)WhT, bh, lg, NACT);
    // masked softmax -> fp32 probabilities           [PDL on head]
    launch_pdl(masked_softmax_h, dim3(BATCH), dim3(256), (size_t)0,
               (const __half*)lg, out, states);
}